// round 5
// baseline (speedup 1.0000x reference)
#include <cuda_runtime.h>
#include <cuda_bf16.h>
#include <cstdint>

#define B_  2
#define LQ  1024
#define LK  2048
#define DM  1024
#define NH  16
#define DH  64
#define BH  (B_*NH)
#define OUT_ELEMS (B_*LQ*DM)

// bf16 hi/lo pools for converted inputs + ctx (elements)
#define P_QUERY 0
#define P_KEY   (2*1024*1024)
#define P_VALUE (6*1024*1024)
#define P_WQ    (10*1024*1024)
#define P_WK    (11*1024*1024)
#define P_WV    (12*1024*1024)
#define P_WO    (13*1024*1024)
#define P_CTX   (14*1024*1024)
#define P_TOTAL (16*1024*1024)

__device__ __align__(256) __nv_bfloat16 g_hi[P_TOTAL];
__device__ __align__(256) __nv_bfloat16 g_lo[P_TOTAL];
__device__ __align__(256) __nv_bfloat16 g_Qhi[BH*LQ*DH];
__device__ __align__(256) __nv_bfloat16 g_Qlo[BH*LQ*DH];
__device__ __align__(256) __nv_bfloat16 g_Khi[BH*LK*DH];
__device__ __align__(256) __nv_bfloat16 g_Klo[BH*LK*DH];
__device__ __align__(256) __nv_bfloat16 g_Vthi[BH*DH*LK];   // [bh, d, t]
__device__ __align__(256) __nv_bfloat16 g_Vtlo[BH*DH*LK];
__device__ __align__(256) float2        g_stats[BH*LQ];     // (rowmax, 1/sum)

// ---------------- low-level helpers ----------------------------------------
__device__ __forceinline__ uint32_t smem_u32(const void* p){
    uint32_t a;
    asm("{ .reg .u64 t; cvta.to.shared.u64 t, %1; cvt.u32.u64 %0, t; }" : "=r"(a) : "l"(p));
    return a;
}
#define CP16(d,s) asm volatile("cp.async.cg.shared.global [%0], [%1], 16;" :: "r"(d), "l"(__cvta_generic_to_global(s)))
#define CPCOMMIT() asm volatile("cp.async.commit_group;" ::: "memory")
#define CPWAIT(n)  asm volatile("cp.async.wait_group %0;" :: "n"(n) : "memory")

__device__ __forceinline__ void ldm_x4(uint32_t* r, uint32_t a){
    asm volatile("ldmatrix.sync.aligned.m8n8.x4.shared.b16 {%0,%1,%2,%3}, [%4];"
        : "=r"(r[0]),"=r"(r[1]),"=r"(r[2]),"=r"(r[3]) : "r"(a));
}
__device__ __forceinline__ void ldm_x2(uint32_t* r, uint32_t a){
    asm volatile("ldmatrix.sync.aligned.m8n8.x2.shared.b16 {%0,%1}, [%2];"
        : "=r"(r[0]),"=r"(r[1]) : "r"(a));
}
__device__ __forceinline__ void mma16816(float* d, const uint32_t* a, const uint32_t* b){
    asm volatile("mma.sync.aligned.m16n8k16.row.col.f32.bf16.bf16.f32 "
        "{%0,%1,%2,%3}, {%4,%5,%6,%7}, {%8,%9}, {%0,%1,%2,%3};"
        : "+f"(d[0]),"+f"(d[1]),"+f"(d[2]),"+f"(d[3])
        : "r"(a[0]),"r"(a[1]),"r"(a[2]),"r"(a[3]), "r"(b[0]),"r"(b[1]));
}
__device__ __forceinline__ void fsplit(float x, __nv_bfloat16& h, __nv_bfloat16& l){
    h = __float2bfloat16(x);
    l = __float2bfloat16(x - __bfloat162float(h));
}
__device__ __forceinline__ uint32_t pack2(__nv_bfloat16 a, __nv_bfloat16 b){
    return (uint32_t)__bfloat16_as_ushort(a) | ((uint32_t)__bfloat16_as_ushort(b) << 16);
}

// ---------------- input conversion fp32 -> bf16 hi/lo -----------------------
__global__ void __launch_bounds__(256) cvt_kernel(const float4* __restrict__ src,
                                                  uint2* __restrict__ hi,
                                                  uint2* __restrict__ lo, int n4)
{
    int i = blockIdx.x*256 + threadIdx.x;
    if (i >= n4) return;
    float4 v = src[i];
    __nv_bfloat16 h0,l0,h1,l1,h2,l2,h3,l3;
    fsplit(v.x,h0,l0); fsplit(v.y,h1,l1); fsplit(v.z,h2,l2); fsplit(v.w,h3,l3);
    hi[i] = make_uint2(pack2(h0,h1), pack2(h2,h3));
    lo[i] = make_uint2(pack2(l0,l1), pack2(l2,l3));
}

// ============================================================================
// Projection GEMM (unchanged from R4): C[128x128] = A @ W^T + bias
// ============================================================================
#define TSTRIDE 144
#define TILESZ  18432
#define PROJ_SMEM (512 + 2*4*TILESZ + 128*132*4)

template<int MODE>
__global__ void __launch_bounds__(256) proj_kernel(
    const __nv_bfloat16* __restrict__ Ah_g, const __nv_bfloat16* __restrict__ Al_g,
    const __nv_bfloat16* __restrict__ Wh_g, const __nv_bfloat16* __restrict__ Wl_g,
    const float* __restrict__ bias, float* __restrict__ outp, int Ltok)
{
    extern __shared__ char smc[];
    const uint32_t sb = smem_u32(smc);
    const uint32_t tbase = sb + 512;
    float* bias_sm = (float*)smc;
    float* stg = (float*)(smc + 512 + 2*4*TILESZ);

    const int tid = threadIdx.x, lane = tid&31, wid = tid>>5;
    const int wm = wid>>1, wn = wid&1;
    const int m0 = blockIdx.y*128, n0 = blockIdx.x*128;

    if (tid < 128) bias_sm[tid] = bias[n0+tid];

    const __nv_bfloat16* gp[4] = {
        Ah_g + (size_t)m0*DM, Al_g + (size_t)m0*DM,
        Wh_g + (size_t)n0*DM, Wl_g + (size_t)n0*DM };

    float acc[2][8][4];
#pragma unroll
    for (int a=0;a<2;a++)
#pragma unroll
        for (int b=0;b<8;b++)
#pragma unroll
            for (int c=0;c<4;c++) acc[a][b][c]=0.f;

    const uint32_t aoff = (uint32_t)((wm*32 + (lane&15))*TSTRIDE + (lane>>4)*16);
    const uint32_t boff = (uint32_t)((wn*64 + (lane&7))*TSTRIDE + ((lane>>3)&1)*16);

#pragma unroll
    for (int t4=0;t4<4;t4++)
#pragma unroll
        for (int i=0;i<4;i++){
            int idx = tid + i*256, row = idx>>3, c = idx&7;
            CP16(tbase + t4*TILESZ + row*TSTRIDE + c*16, gp[t4] + (size_t)row*DM + c*8);
        }
    CPCOMMIT();

    for (int ck=0; ck<16; ck++){
        if (ck+1 < 16){
            uint32_t st1 = tbase + ((ck+1)&1)*(4*TILESZ);
#pragma unroll
            for (int t4=0;t4<4;t4++)
#pragma unroll
                for (int i=0;i<4;i++){
                    int idx = tid + i*256, row = idx>>3, c = idx&7;
                    CP16(st1 + t4*TILESZ + row*TSTRIDE + c*16,
                         gp[t4] + (size_t)row*DM + (ck+1)*64 + c*8);
                }
            CPCOMMIT();
            CPWAIT(1);
        } else {
            CPWAIT(0);
        }
        __syncthreads();

        const uint32_t TA  = tbase + (ck&1)*(4*TILESZ);
        const uint32_t TAl = TA + TILESZ, TW = TA + 2*TILESZ, TWl = TA + 3*TILESZ;
#pragma unroll
        for (int ks=0;ks<4;ks++){
            uint32_t ah[2][4], al[2][4];
            ldm_x4(ah[0], TA  + aoff + ks*32);
            ldm_x4(ah[1], TA  + aoff + 16*TSTRIDE + ks*32);
            ldm_x4(al[0], TAl + aoff + ks*32);
            ldm_x4(al[1], TAl + aoff + 16*TSTRIDE + ks*32);
#pragma unroll
            for (int nt=0;nt<8;nt++){
                uint32_t bh[2], bl[2];
                ldm_x2(bh, TW  + boff + nt*8*TSTRIDE + ks*32);
                ldm_x2(bl, TWl + boff + nt*8*TSTRIDE + ks*32);
#pragma unroll
                for (int mt=0;mt<2;mt++){
                    mma16816(acc[mt][nt], ah[mt], bh);
                    mma16816(acc[mt][nt], ah[mt], bl);
                    mma16816(acc[mt][nt], al[mt], bh);
                }
            }
        }
        __syncthreads();
    }

    {
        const int g = lane>>2, tg = lane&3;
#pragma unroll
        for (int mt=0;mt<2;mt++)
#pragma unroll
            for (int nt=0;nt<8;nt++){
                int row = wm*32 + mt*16 + g;
                int col = wn*64 + nt*8 + tg*2;
                float b0 = bias_sm[col], b1 = bias_sm[col+1];
                float v0 = acc[mt][nt][0]+b0, v1 = acc[mt][nt][1]+b1;
                float v2 = acc[mt][nt][2]+b0, v3 = acc[mt][nt][3]+b1;
                if (MODE==0){ v0*=0.125f; v1*=0.125f; v2*=0.125f; v3*=0.125f; }
                stg[row*132+col] = v0;  stg[row*132+col+1] = v1;
                stg[(row+8)*132+col] = v2; stg[(row+8)*132+col+1] = v3;
            }
    }
    __syncthreads();

    if (MODE==3){
        const int r2 = tid>>1, hf = tid&1;
        const float* srow = stg + r2*132 + hf*64;
        float* drow = outp + (size_t)(m0+r2)*DM + n0 + hf*64;
#pragma unroll
        for (int j=0;j<16;j++) *(float4*)(drow + j*4) = *(const float4*)(srow + j*4);
    } else if (MODE<2){
        const int r2 = tid>>1, hf = tid&1;
        const int rowg = m0 + r2;
        const int b = rowg / Ltok, tok = rowg - b*Ltok;
        const int h = (n0>>6) + hf;
        const float* srow = stg + r2*132 + hf*64;
        __nv_bfloat16* gh = ((MODE==0)? g_Qhi : g_Khi) + ((size_t)(b*NH+h)*Ltok + tok)*DH;
        __nv_bfloat16* gl = ((MODE==0)? g_Qlo : g_Klo) + ((size_t)(b*NH+h)*Ltok + tok)*DH;
#pragma unroll
        for (int j=0;j<8;j++){
            __nv_bfloat16 h0,l0,h1,l1,h2,l2,h3,l3,h4,l4,h5,l5,h6,l6,h7,l7;
            fsplit(srow[j*8+0],h0,l0); fsplit(srow[j*8+1],h1,l1);
            fsplit(srow[j*8+2],h2,l2); fsplit(srow[j*8+3],h3,l3);
            fsplit(srow[j*8+4],h4,l4); fsplit(srow[j*8+5],h5,l5);
            fsplit(srow[j*8+6],h6,l6); fsplit(srow[j*8+7],h7,l7);
            ((uint4*)gh)[j] = make_uint4(pack2(h0,h1),pack2(h2,h3),pack2(h4,h5),pack2(h6,h7));
            ((uint4*)gl)[j] = make_uint4(pack2(l0,l1),pack2(l2,l3),pack2(l4,l5),pack2(l6,l7));
        }
    } else {
        const int dl = tid>>1, th = tid&1;
        const int dg = n0 + dl, h = dg>>6, dd = dg&63;
        const int b = m0 / Ltok, toff = m0 - b*Ltok;
        __nv_bfloat16* vh = g_Vthi + ((size_t)(b*NH+h)*DH + dd)*LK + toff + th*64;
        __nv_bfloat16* vl = g_Vtlo + ((size_t)(b*NH+h)*DH + dd)*LK + toff + th*64;
#pragma unroll
        for (int j=0;j<16;j++){
            int t4 = th*64 + j*4;
            __nv_bfloat16 h0,l0,h1,l1,h2,l2,h3,l3;
            fsplit(stg[(t4+0)*132+dl],h0,l0);
            fsplit(stg[(t4+1)*132+dl],h1,l1);
            fsplit(stg[(t4+2)*132+dl],h2,l2);
            fsplit(stg[(t4+3)*132+dl],h3,l3);
            ((uint2*)vh)[j] = make_uint2(pack2(h0,h1), pack2(h2,h3));
            ((uint2*)vl)[j] = make_uint2(pack2(l0,l1), pack2(l2,l3));
        }
    }
}

// ============================================================================
// Scores v2: per CTA = (q-tile 128, bh); full k row (16 subtiles of 128).
// Writes raw masked scores (fp32) to attn region; computes online-softmax
// row stats -> g_stats = (rowmax, 1/rowsum).
// smem: Qh,Ql @0 (36864) | K dbl 2x{Kh,Kl} @36864 (73728). 110592 B.
// ============================================================================
#define SC2_SMEM (2*TILESZ + 2*2*TILESZ)
__global__ void __launch_bounds__(256) scores_kernel(
    const float* __restrict__ bias, const int* __restrict__ mask,
    float* __restrict__ attn)
{
    extern __shared__ char smc[];
    __shared__ float2 s_stats[2][128];
    const uint32_t sb = smem_u32(smc);
    const int tid = threadIdx.x, lane = tid&31, wid = tid>>5;
    const int wm = wid>>1, wn = wid&1, g = lane>>2, tg = lane&3;
    const int q0 = blockIdx.x*128, bh = blockIdx.y, b = bh>>4;

    const uint32_t TQh = sb, TQl = sb + TILESZ;
    const uint32_t TKbase = sb + 2*TILESZ;

    const __nv_bfloat16* Qh = g_Qhi + ((size_t)bh*LQ + q0)*DH;
    const __nv_bfloat16* Ql = g_Qlo + ((size_t)bh*LQ + q0)*DH;
    const __nv_bfloat16* Kh = g_Khi + (size_t)bh*LK*DH;
    const __nv_bfloat16* Kl = g_Klo + (size_t)bh*LK*DH;

    // load Q tiles + prefetch K chunk 0
#pragma unroll
    for (int i=0;i<4;i++){
        int idx = tid + i*256, row = idx>>3, c = idx&7;
        CP16(TQh + row*TSTRIDE + c*16, Qh + (size_t)row*DH + c*8);
        CP16(TQl + row*TSTRIDE + c*16, Ql + (size_t)row*DH + c*8);
        CP16(TKbase + row*TSTRIDE + c*16,          Kh + (size_t)row*DH + c*8);
        CP16(TKbase + TILESZ + row*TSTRIDE + c*16, Kl + (size_t)row*DH + c*8);
    }
    CPCOMMIT();

    const uint32_t aoff = (uint32_t)((wm*32 + (lane&15))*TSTRIDE + (lane>>4)*16);
    const uint32_t boff = (uint32_t)((wn*64 + (lane&7))*TSTRIDE + ((lane>>3)&1)*16);

    float m_run[2][2], s_run[2][2];
#pragma unroll
    for (int a=0;a<2;a++){ m_run[a][0]=-3e38f; m_run[a][1]=-3e38f; s_run[a][0]=0.f; s_run[a][1]=0.f; }

    for (int kt=0; kt<16; kt++){
        if (kt+1 < 16){
            uint32_t st1 = TKbase + ((kt+1)&1)*(2*TILESZ);
#pragma unroll
            for (int i=0;i<4;i++){
                int idx = tid + i*256, row = idx>>3, c = idx&7;
                CP16(st1 + row*TSTRIDE + c*16,          Kh + ((size_t)(kt+1)*128+row)*DH + c*8);
                CP16(st1 + TILESZ + row*TSTRIDE + c*16, Kl + ((size_t)(kt+1)*128+row)*DH + c*8);
            }
            CPCOMMIT();
            CPWAIT(1);
        } else {
            CPWAIT(0);
        }
        __syncthreads();

        float acc[2][8][4];
#pragma unroll
        for (int a=0;a<2;a++)
#pragma unroll
            for (int c=0;c<8;c++)
#pragma unroll
                for (int d=0;d<4;d++) acc[a][c][d]=0.f;

        const uint32_t TKh = TKbase + (kt&1)*(2*TILESZ), TKl = TKh + TILESZ;
#pragma unroll
        for (int ks=0;ks<4;ks++){
            uint32_t ah[2][4], al[2][4];
            ldm_x4(ah[0], TQh + aoff + ks*32);
            ldm_x4(ah[1], TQh + aoff + 16*TSTRIDE + ks*32);
            ldm_x4(al[0], TQl + aoff + ks*32);
            ldm_x4(al[1], TQl + aoff + 16*TSTRIDE + ks*32);
#pragma unroll
            for (int nt=0;nt<8;nt++){
                uint32_t bh2[2], bl2[2];
                ldm_x2(bh2, TKh + boff + nt*8*TSTRIDE + ks*32);
                ldm_x2(bl2, TKl + boff + nt*8*TSTRIDE + ks*32);
#pragma unroll
                for (int mt=0;mt<2;mt++){
                    mma16816(acc[mt][nt], ah[mt], bh2);
                    mma16816(acc[mt][nt], ah[mt], bl2);
                    mma16816(acc[mt][nt], al[mt], bh2);
                }
            }
        }
        __syncthreads();

        // epilogue: bias + mask, tile row max
        float tmax[2][2] = {{-3e38f,-3e38f},{-3e38f,-3e38f}};
#pragma unroll
        for (int mt=0;mt<2;mt++){
            const int q = q0 + wm*32 + mt*16 + g;
            const size_t bb = (size_t)(bh*LQ + q)*LK + kt*128 + wn*64;
            const size_t mb = (size_t)(b*LQ  + q)*LK + kt*128 + wn*64;
#pragma unroll
            for (int nt=0;nt<8;nt++){
                const int co = nt*8 + tg*2;
                float2 b0 = *(const float2*)(bias + bb + co);
                float2 b1 = *(const float2*)(bias + bb + 8*LK + co);
                int2  mm0 = *(const int2*)(mask + mb + co);
                int2  mm1 = *(const int2*)(mask + mb + 8*(size_t)LK + co);
                float v0 = mm0.x ? acc[mt][nt][0]+b0.x : -1e9f;
                float v1 = mm0.y ? acc[mt][nt][1]+b0.y : -1e9f;
                float v2 = mm1.x ? acc[mt][nt][2]+b1.x : -1e9f;
                float v3 = mm1.y ? acc[mt][nt][3]+b1.y : -1e9f;
                acc[mt][nt][0]=v0; acc[mt][nt][1]=v1; acc[mt][nt][2]=v2; acc[mt][nt][3]=v3;
                tmax[mt][0] = fmaxf(tmax[mt][0], fmaxf(v0,v1));
                tmax[mt][1] = fmaxf(tmax[mt][1], fmaxf(v2,v3));
            }
        }
#pragma unroll
        for (int mt=0;mt<2;mt++)
#pragma unroll
            for (int hh=0;hh<2;hh++){
                float t = tmax[mt][hh];
                t = fmaxf(t, __shfl_xor_sync(0xffffffffu, t, 1));
                t = fmaxf(t, __shfl_xor_sync(0xffffffffu, t, 2));
                float mn = fmaxf(m_run[mt][hh], t);
                s_run[mt][hh] *= __expf(m_run[mt][hh] - mn);
                m_run[mt][hh] = mn;
                tmax[mt][hh] = mn;
            }
        // exp-sum + raw score write
#pragma unroll
        for (int mt=0;mt<2;mt++){
            const int q = q0 + wm*32 + mt*16 + g;
            float* ar = attn + (size_t)(bh*LQ + q)*LK + kt*128 + wn*64;
            float ps0 = 0.f, ps1 = 0.f;
            const float mn0 = tmax[mt][0], mn1 = tmax[mt][1];
#pragma unroll
            for (int nt=0;nt<8;nt++){
                const int co = nt*8 + tg*2;
                ps0 += __expf(acc[mt][nt][0]-mn0) + __expf(acc[mt][nt][1]-mn0);
                ps1 += __expf(acc[mt][nt][2]-mn1) + __expf(acc[mt][nt][3]-mn1);
                *(float2*)(ar + co)        = make_float2(acc[mt][nt][0], acc[mt][nt][1]);
                *(float2*)(ar + 8*LK + co) = make_float2(acc[mt][nt][2], acc[mt][nt][3]);
            }
            ps0 += __shfl_xor_sync(0xffffffffu, ps0, 1);
            ps0 += __shfl_xor_sync(0xffffffffu, ps0, 2);
            ps1 += __shfl_xor_sync(0xffffffffu, ps1, 1);
            ps1 += __shfl_xor_sync(0xffffffffu, ps1, 2);
            s_run[mt][0] += ps0;
            s_run[mt][1] += ps1;
        }
    }

    // merge across wn warp pairs
    if (tg == 0){
#pragma unroll
        for (int mt=0;mt<2;mt++)
#pragma unroll
            for (int hh=0;hh<2;hh++){
                int row = wm*32 + mt*16 + g + hh*8;
                s_stats[wn][row] = make_float2(m_run[mt][hh], s_run[mt][hh]);
            }
    }
    __syncthreads();
    if (tid < 128){
        float2 a = s_stats[0][tid], c = s_stats[1][tid];
        float m = fmaxf(a.x, c.x);
        float s = a.y*__expf(a.x-m) + c.y*__expf(c.x-m);
        g_stats[(size_t)bh*LQ + q0 + tid] = make_float2(m, 1.f/s);
    }
}

// ============================================================================
// PV v2: reads raw scores, applies p=exp(s-m)*inv in-place (normalized attn
// output written back), MMA P@V^T -> ctx hi/lo.
// smem: Ph@0, Pl@18432, Vh@36864, Vl@46080, stage fp32 @55296. 90112 B.
// ============================================================================
#define PV_SMEM (2*TILESZ + 2*9216 + 128*68*4)
__global__ void __launch_bounds__(256) pv_kernel(float* __restrict__ attn)
{
    extern __shared__ char smc[];
    const uint32_t sb = smem_u32(smc);
    float* stg = (float*)(smc + 2*TILESZ + 2*9216);
    const int tid = threadIdx.x, lane = tid&31, wid = tid>>5;
    const int wm = wid>>1, wn = wid&1;
    const int q0 = blockIdx.x*128, bh = blockIdx.y, b = bh>>4, h = bh&15;

    const uint32_t TPh = sb, TPl = sb+TILESZ, TVh = sb+2*TILESZ, TVl = TVh+9216;
    const int crow = tid>>1, chf = tid&1;    // conversion: row, col-half (32)
    float* Prow = attn + ((size_t)bh*LQ + q0 + crow)*LK + chf*32;
    const float2 st = g_stats[(size_t)bh*LQ + q0 + crow];
    const float rm = st.x, rinv = st.y;

    const __nv_bfloat16* Vhg = g_Vthi + (size_t)bh*DH*LK;
    const __nv_bfloat16* Vlg = g_Vtlo + (size_t)bh*DH*LK;

    float acc[2][4][4];
#pragma unroll
    for (int a=0;a<2;a++)
#pragma unroll
        for (int c=0;c<4;c++)
#pragma unroll
            for (int d=0;d<4;d++) acc[a][c][d]=0.f;

    const uint32_t aoff = (uint32_t)((wm*32 + (lane&15))*TSTRIDE + (lane>>4)*16);
    const uint32_t boff = (uint32_t)((wn*32 + (lane&7))*TSTRIDE + ((lane>>3)&1)*16);

    for (int ck=0; ck<32; ck++){
        const int t0 = ck*64;
        __syncthreads();
        // convert raw scores -> p, write back normalized, build P hi/lo tiles
        {
            char* ph = smc + crow*TSTRIDE + chf*64;
            char* pl = smc + TILESZ + crow*TSTRIDE + chf*64;
#pragma unroll
            for (int j=0;j<8;j++){
                float4 v = *(const float4*)(Prow + t0 + j*4);
                float p0 = __expf(v.x - rm)*rinv;
                float p1 = __expf(v.y - rm)*rinv;
                float p2 = __expf(v.z - rm)*rinv;
                float p3 = __expf(v.w - rm)*rinv;
                *(float4*)(Prow + t0 + j*4) = make_float4(p0,p1,p2,p3);
                __nv_bfloat16 h0,l0,h1,l1,h2,l2,h3,l3;
                fsplit(p0,h0,l0); fsplit(p1,h1,l1); fsplit(p2,h2,l2); fsplit(p3,h3,l3);
                *(uint2*)(ph + j*8) = make_uint2(pack2(h0,h1), pack2(h2,h3));
                *(uint2*)(pl + j*8) = make_uint2(pack2(l0,l1), pack2(l2,l3));
            }
        }
        // V tiles
#pragma unroll
        for (int i=0;i<2;i++){
            int idx = tid + i*256, row = idx>>3, c = idx&7;
            CP16(TVh + row*TSTRIDE + c*16, Vhg + (size_t)row*LK + t0 + c*8);
            CP16(TVl + row*TSTRIDE + c*16, Vlg + (size_t)row*LK + t0 + c*8);
        }
        CPCOMMIT(); CPWAIT(0);
        __syncthreads();
#pragma unroll
        for (int ks=0;ks<4;ks++){
            uint32_t ah[2][4], al[2][4];
            ldm_x4(ah[0], TPh + aoff + ks*32);
            ldm_x4(ah[1], TPh + aoff + 16*TSTRIDE + ks*32);
            ldm_x4(al[0], TPl + aoff + ks*32);
            ldm_x4(al[1], TPl + aoff + 16*TSTRIDE + ks*32);
#pragma unroll
            for (int nt=0;nt<4;nt++){
                uint32_t bh2[2], bl2[2];
                ldm_x2(bh2, TVh + boff + nt*8*TSTRIDE + ks*32);
                ldm_x2(bl2, TVl + boff + nt*8*TSTRIDE + ks*32);
#pragma unroll
                for (int mt=0;mt<2;mt++){
                    mma16816(acc[mt][nt], ah[mt], bh2);
                    mma16816(acc[mt][nt], ah[mt], bl2);
                    mma16816(acc[mt][nt], al[mt], bh2);
                }
            }
        }
    }
    __syncthreads();
    {
        const int g = lane>>2, tg = lane&3;
#pragma unroll
        for (int mt=0;mt<2;mt++)
#pragma unroll
            for (int nt=0;nt<4;nt++){
                int row = wm*32 + mt*16 + g;
                int col = wn*32 + nt*8 + tg*2;
                stg[row*68+col] = acc[mt][nt][0];  stg[row*68+col+1] = acc[mt][nt][1];
                stg[(row+8)*68+col] = acc[mt][nt][2]; stg[(row+8)*68+col+1] = acc[mt][nt][3];
            }
    }
    __syncthreads();
    {
        const int r2 = tid>>1, hf = tid&1;
        const float* srow = stg + r2*68 + hf*32;
        size_t base = ((size_t)(b*LQ + q0 + r2))*DM + h*DH + hf*32;
        __nv_bfloat16* ch = g_hi + P_CTX + base;
        __nv_bfloat16* cl = g_lo + P_CTX + base;
#pragma unroll
        for (int j=0;j<4;j++){
            __nv_bfloat16 h0,l0,h1,l1,h2,l2,h3,l3,h4,l4,h5,l5,h6,l6,h7,l7;
            fsplit(srow[j*8+0],h0,l0); fsplit(srow[j*8+1],h1,l1);
            fsplit(srow[j*8+2],h2,l2); fsplit(srow[j*8+3],h3,l3);
            fsplit(srow[j*8+4],h4,l4); fsplit(srow[j*8+5],h5,l5);
            fsplit(srow[j*8+6],h6,l6); fsplit(srow[j*8+7],h7,l7);
            ((uint4*)ch)[j] = make_uint4(pack2(h0,h1),pack2(h2,h3),pack2(h4,h5),pack2(h6,h7));
            ((uint4*)cl)[j] = make_uint4(pack2(l0,l1),pack2(l2,l3),pack2(l4,l5),pack2(l6,l7));
        }
    }
}

// ============================================================================
extern "C" void kernel_launch(void* const* d_in, const int* in_sizes, int n_in,
                              void* d_out, int out_size)
{
    const float* query = (const float*)d_in[0];
    const float* key   = (const float*)d_in[1];
    const float* value = (const float*)d_in[2];
    const int*   mask  = (const int*)  d_in[3];
    const float* abias = (const float*)d_in[4];
    const float* Wq = (const float*)d_in[5];
    const float* bq = (const float*)d_in[6];
    const float* Wk = (const float*)d_in[7];
    const float* bk = (const float*)d_in[8];
    const float* Wv = (const float*)d_in[9];
    const float* bv = (const float*)d_in[10];
    const float* Wo = (const float*)d_in[11];
    const float* bo = (const float*)d_in[12];
    float* out  = (float*)d_out;
    float* attn = out + OUT_ELEMS;

    __nv_bfloat16 *hi, *lo;
    cudaGetSymbolAddress((void**)&hi, g_hi);
    cudaGetSymbolAddress((void**)&lo, g_lo);

    cudaFuncSetAttribute(proj_kernel<0>, cudaFuncAttributeMaxDynamicSharedMemorySize, PROJ_SMEM);
    cudaFuncSetAttribute(proj_kernel<1>, cudaFuncAttributeMaxDynamicSharedMemorySize, PROJ_SMEM);
    cudaFuncSetAttribute(proj_kernel<2>, cudaFuncAttributeMaxDynamicSharedMemorySize, PROJ_SMEM);
    cudaFuncSetAttribute(proj_kernel<3>, cudaFuncAttributeMaxDynamicSharedMemorySize, PROJ_SMEM);
    cudaFuncSetAttribute(scores_kernel,  cudaFuncAttributeMaxDynamicSharedMemorySize, SC2_SMEM);
    cudaFuncSetAttribute(pv_kernel,      cudaFuncAttributeMaxDynamicSharedMemorySize, PV_SMEM);

    struct { const float* s; int off; int n; } cv[7] = {
        {query, P_QUERY, B_*LQ*DM}, {key, P_KEY, B_*LK*DM}, {value, P_VALUE, B_*LK*DM},
        {Wq, P_WQ, DM*DM}, {Wk, P_WK, DM*DM}, {Wv, P_WV, DM*DM}, {Wo, P_WO, DM*DM}};
    for (int i=0;i<7;i++){
        int n4 = cv[i].n/4;
        cvt_kernel<<<(n4+255)/256, 256>>>((const float4*)cv[i].s,
            (uint2*)(hi+cv[i].off), (uint2*)(lo+cv[i].off), n4);
    }

    proj_kernel<0><<<dim3(8,16), 256, PROJ_SMEM>>>(hi+P_QUERY, lo+P_QUERY, hi+P_WQ, lo+P_WQ, bq, nullptr, LQ);
    proj_kernel<1><<<dim3(8,32), 256, PROJ_SMEM>>>(hi+P_KEY,   lo+P_KEY,   hi+P_WK, lo+P_WK, bk, nullptr, LK);
    proj_kernel<2><<<dim3(8,32), 256, PROJ_SMEM>>>(hi+P_VALUE, lo+P_VALUE, hi+P_WV, lo+P_WV, bv, nullptr, LK);

    scores_kernel<<<dim3(LQ/128, BH), 256, SC2_SMEM>>>(abias, mask, attn);
    pv_kernel<<<dim3(LQ/128, BH), 256, PV_SMEM>>>(attn);

    proj_kernel<3><<<dim3(8,16), 256, PROJ_SMEM>>>(hi+P_CTX, lo+P_CTX, hi+P_WO, lo+P_WO, bo, out, LQ);
}

// round 6
// speedup vs baseline: 2.0617x; 2.0617x over previous
#include <cuda_runtime.h>
#include <cuda_bf16.h>
#include <cstdint>

#define B_  2
#define LQ  1024
#define LK  2048
#define DM  1024
#define NH  16
#define DH  64
#define BH  (B_*NH)
#define OUT_ELEMS (B_*LQ*DM)

// bf16 hi/lo pools for converted inputs + ctx (elements)
#define P_QUERY 0
#define P_KEY   (2*1024*1024)
#define P_VALUE (6*1024*1024)
#define P_WQ    (10*1024*1024)
#define P_WK    (11*1024*1024)
#define P_WV    (12*1024*1024)
#define P_WO    (13*1024*1024)
#define P_CTX   (14*1024*1024)
#define P_TOTAL (16*1024*1024)

__device__ __align__(256) __nv_bfloat16 g_hi[P_TOTAL];
__device__ __align__(256) __nv_bfloat16 g_lo[P_TOTAL];
__device__ __align__(256) __nv_bfloat16 g_Qhi[BH*LQ*DH];
__device__ __align__(256) __nv_bfloat16 g_Qlo[BH*LQ*DH];
__device__ __align__(256) __nv_bfloat16 g_Khi[BH*LK*DH];
__device__ __align__(256) __nv_bfloat16 g_Klo[BH*LK*DH];
__device__ __align__(256) __nv_bfloat16 g_Vthi[BH*DH*LK];   // [bh, d, t]
__device__ __align__(256) __nv_bfloat16 g_Vtlo[BH*DH*LK];
__device__ __align__(256) float2        g_pstats[BH*LQ*16]; // per-tile (max, sumexp)
__device__ __align__(256) float         g_scale[BH*LQ*16];  // exp(m_t-m)/S

// ---------------- low-level helpers ----------------------------------------
__device__ __forceinline__ uint32_t smem_u32(const void* p){
    uint32_t a;
    asm("{ .reg .u64 t; cvta.to.shared.u64 t, %1; cvt.u32.u64 %0, t; }" : "=r"(a) : "l"(p));
    return a;
}
#define CP16(d,s) asm volatile("cp.async.cg.shared.global [%0], [%1], 16;" :: "r"(d), "l"(__cvta_generic_to_global(s)))
#define CPCOMMIT() asm volatile("cp.async.commit_group;" ::: "memory")
#define CPWAIT(n)  asm volatile("cp.async.wait_group %0;" :: "n"(n) : "memory")

__device__ __forceinline__ void ldm_x4(uint32_t* r, uint32_t a){
    asm volatile("ldmatrix.sync.aligned.m8n8.x4.shared.b16 {%0,%1,%2,%3}, [%4];"
        : "=r"(r[0]),"=r"(r[1]),"=r"(r[2]),"=r"(r[3]) : "r"(a));
}
__device__ __forceinline__ void ldm_x2(uint32_t* r, uint32_t a){
    asm volatile("ldmatrix.sync.aligned.m8n8.x2.shared.b16 {%0,%1}, [%2];"
        : "=r"(r[0]),"=r"(r[1]) : "r"(a));
}
__device__ __forceinline__ void mma16816(float* d, const uint32_t* a, const uint32_t* b){
    asm volatile("mma.sync.aligned.m16n8k16.row.col.f32.bf16.bf16.f32 "
        "{%0,%1,%2,%3}, {%4,%5,%6,%7}, {%8,%9}, {%0,%1,%2,%3};"
        : "+f"(d[0]),"+f"(d[1]),"+f"(d[2]),"+f"(d[3])
        : "r"(a[0]),"r"(a[1]),"r"(a[2]),"r"(a[3]), "r"(b[0]),"r"(b[1]));
}
__device__ __forceinline__ void fsplit(float x, __nv_bfloat16& h, __nv_bfloat16& l){
    h = __float2bfloat16(x);
    l = __float2bfloat16(x - __bfloat162float(h));
}
__device__ __forceinline__ uint32_t pack2(__nv_bfloat16 a, __nv_bfloat16 b){
    return (uint32_t)__bfloat16_as_ushort(a) | ((uint32_t)__bfloat16_as_ushort(b) << 16);
}

// ---------------- input conversion fp32 -> bf16 hi/lo -----------------------
__global__ void __launch_bounds__(256) cvt_kernel(const float4* __restrict__ src,
                                                  uint2* __restrict__ hi,
                                                  uint2* __restrict__ lo, int n4)
{
    int i = blockIdx.x*256 + threadIdx.x;
    if (i >= n4) return;
    float4 v = src[i];
    __nv_bfloat16 h0,l0,h1,l1,h2,l2,h3,l3;
    fsplit(v.x,h0,l0); fsplit(v.y,h1,l1); fsplit(v.z,h2,l2); fsplit(v.w,h3,l3);
    hi[i] = make_uint2(pack2(h0,h1), pack2(h2,h3));
    lo[i] = make_uint2(pack2(l0,l1), pack2(l2,l3));
}

// ============================================================================
// Projection GEMM (unchanged from R4): C[128x128] = A @ W^T + bias
// ============================================================================
#define TSTRIDE 144
#define TILESZ  18432
#define PROJ_SMEM (512 + 2*4*TILESZ + 128*132*4)

template<int MODE>
__global__ void __launch_bounds__(256) proj_kernel(
    const __nv_bfloat16* __restrict__ Ah_g, const __nv_bfloat16* __restrict__ Al_g,
    const __nv_bfloat16* __restrict__ Wh_g, const __nv_bfloat16* __restrict__ Wl_g,
    const float* __restrict__ bias, float* __restrict__ outp, int Ltok)
{
    extern __shared__ char smc[];
    const uint32_t sb = smem_u32(smc);
    const uint32_t tbase = sb + 512;
    float* bias_sm = (float*)smc;
    float* stg = (float*)(smc + 512 + 2*4*TILESZ);

    const int tid = threadIdx.x, lane = tid&31, wid = tid>>5;
    const int wm = wid>>1, wn = wid&1;
    const int m0 = blockIdx.y*128, n0 = blockIdx.x*128;

    if (tid < 128) bias_sm[tid] = bias[n0+tid];

    const __nv_bfloat16* gp[4] = {
        Ah_g + (size_t)m0*DM, Al_g + (size_t)m0*DM,
        Wh_g + (size_t)n0*DM, Wl_g + (size_t)n0*DM };

    float acc[2][8][4];
#pragma unroll
    for (int a=0;a<2;a++)
#pragma unroll
        for (int b=0;b<8;b++)
#pragma unroll
            for (int c=0;c<4;c++) acc[a][b][c]=0.f;

    const uint32_t aoff = (uint32_t)((wm*32 + (lane&15))*TSTRIDE + (lane>>4)*16);
    const uint32_t boff = (uint32_t)((wn*64 + (lane&7))*TSTRIDE + ((lane>>3)&1)*16);

#pragma unroll
    for (int t4=0;t4<4;t4++)
#pragma unroll
        for (int i=0;i<4;i++){
            int idx = tid + i*256, row = idx>>3, c = idx&7;
            CP16(tbase + t4*TILESZ + row*TSTRIDE + c*16, gp[t4] + (size_t)row*DM + c*8);
        }
    CPCOMMIT();

    for (int ck=0; ck<16; ck++){
        if (ck+1 < 16){
            uint32_t st1 = tbase + ((ck+1)&1)*(4*TILESZ);
#pragma unroll
            for (int t4=0;t4<4;t4++)
#pragma unroll
                for (int i=0;i<4;i++){
                    int idx = tid + i*256, row = idx>>3, c = idx&7;
                    CP16(st1 + t4*TILESZ + row*TSTRIDE + c*16,
                         gp[t4] + (size_t)row*DM + (ck+1)*64 + c*8);
                }
            CPCOMMIT();
            CPWAIT(1);
        } else {
            CPWAIT(0);
        }
        __syncthreads();

        const uint32_t TA  = tbase + (ck&1)*(4*TILESZ);
        const uint32_t TAl = TA + TILESZ, TW = TA + 2*TILESZ, TWl = TA + 3*TILESZ;
#pragma unroll
        for (int ks=0;ks<4;ks++){
            uint32_t ah[2][4], al[2][4];
            ldm_x4(ah[0], TA  + aoff + ks*32);
            ldm_x4(ah[1], TA  + aoff + 16*TSTRIDE + ks*32);
            ldm_x4(al[0], TAl + aoff + ks*32);
            ldm_x4(al[1], TAl + aoff + 16*TSTRIDE + ks*32);
#pragma unroll
            for (int nt=0;nt<8;nt++){
                uint32_t bh[2], bl[2];
                ldm_x2(bh, TW  + boff + nt*8*TSTRIDE + ks*32);
                ldm_x2(bl, TWl + boff + nt*8*TSTRIDE + ks*32);
#pragma unroll
                for (int mt=0;mt<2;mt++){
                    mma16816(acc[mt][nt], ah[mt], bh);
                    mma16816(acc[mt][nt], ah[mt], bl);
                    mma16816(acc[mt][nt], al[mt], bh);
                }
            }
        }
        __syncthreads();
    }

    {
        const int g = lane>>2, tg = lane&3;
#pragma unroll
        for (int mt=0;mt<2;mt++)
#pragma unroll
            for (int nt=0;nt<8;nt++){
                int row = wm*32 + mt*16 + g;
                int col = wn*64 + nt*8 + tg*2;
                float b0 = bias_sm[col], b1 = bias_sm[col+1];
                float v0 = acc[mt][nt][0]+b0, v1 = acc[mt][nt][1]+b1;
                float v2 = acc[mt][nt][2]+b0, v3 = acc[mt][nt][3]+b1;
                if (MODE==0){ v0*=0.125f; v1*=0.125f; v2*=0.125f; v3*=0.125f; }
                stg[row*132+col] = v0;  stg[row*132+col+1] = v1;
                stg[(row+8)*132+col] = v2; stg[(row+8)*132+col+1] = v3;
            }
    }
    __syncthreads();

    if (MODE==3){
        const int r2 = tid>>1, hf = tid&1;
        const float* srow = stg + r2*132 + hf*64;
        float* drow = outp + (size_t)(m0+r2)*DM + n0 + hf*64;
#pragma unroll
        for (int j=0;j<16;j++) *(float4*)(drow + j*4) = *(const float4*)(srow + j*4);
    } else if (MODE<2){
        const int r2 = tid>>1, hf = tid&1;
        const int rowg = m0 + r2;
        const int b = rowg / Ltok, tok = rowg - b*Ltok;
        const int h = (n0>>6) + hf;
        const float* srow = stg + r2*132 + hf*64;
        __nv_bfloat16* gh = ((MODE==0)? g_Qhi : g_Khi) + ((size_t)(b*NH+h)*Ltok + tok)*DH;
        __nv_bfloat16* gl = ((MODE==0)? g_Qlo : g_Klo) + ((size_t)(b*NH+h)*Ltok + tok)*DH;
#pragma unroll
        for (int j=0;j<8;j++){
            __nv_bfloat16 h0,l0,h1,l1,h2,l2,h3,l3,h4,l4,h5,l5,h6,l6,h7,l7;
            fsplit(srow[j*8+0],h0,l0); fsplit(srow[j*8+1],h1,l1);
            fsplit(srow[j*8+2],h2,l2); fsplit(srow[j*8+3],h3,l3);
            fsplit(srow[j*8+4],h4,l4); fsplit(srow[j*8+5],h5,l5);
            fsplit(srow[j*8+6],h6,l6); fsplit(srow[j*8+7],h7,l7);
            ((uint4*)gh)[j] = make_uint4(pack2(h0,h1),pack2(h2,h3),pack2(h4,h5),pack2(h6,h7));
            ((uint4*)gl)[j] = make_uint4(pack2(l0,l1),pack2(l2,l3),pack2(l4,l5),pack2(l6,l7));
        }
    } else {
        const int dl = tid>>1, th = tid&1;
        const int dg = n0 + dl, h = dg>>6, dd = dg&63;
        const int b = m0 / Ltok, toff = m0 - b*Ltok;
        __nv_bfloat16* vh = g_Vthi + ((size_t)(b*NH+h)*DH + dd)*LK + toff + th*64;
        __nv_bfloat16* vl = g_Vtlo + ((size_t)(b*NH+h)*DH + dd)*LK + toff + th*64;
#pragma unroll
        for (int j=0;j<16;j++){
            int t4 = th*64 + j*4;
            __nv_bfloat16 h0,l0,h1,l1,h2,l2,h3,l3;
            fsplit(stg[(t4+0)*132+dl],h0,l0);
            fsplit(stg[(t4+1)*132+dl],h1,l1);
            fsplit(stg[(t4+2)*132+dl],h2,l2);
            fsplit(stg[(t4+3)*132+dl],h3,l3);
            ((uint2*)vh)[j] = make_uint2(pack2(h0,h1), pack2(h2,h3));
            ((uint2*)vl)[j] = make_uint2(pack2(l0,l1), pack2(l2,l3));
        }
    }
}

// ============================================================================
// Scores (R4 tile grid): S = Q@K^T, then epilogue applies bias+mask, computes
// per-tile row max, writes exp(s-m_tile) to attn, partial (m,sum) -> g_pstats.
// ============================================================================
#define SC_SMEM (4*TILESZ + 128*132*4)
__global__ void __launch_bounds__(256) scores_kernel(
    const float* __restrict__ bias, const int* __restrict__ mask,
    float* __restrict__ attn)
{
    extern __shared__ char smc[];
    const uint32_t sb = smem_u32(smc);
    float* stg = (float*)(smc + 4*TILESZ);
    const int tid = threadIdx.x, lane = tid&31, wid = tid>>5;
    const int wm = wid>>1, wn = wid&1;
    const int k0 = blockIdx.x*128, q0 = blockIdx.y*128, bh = blockIdx.z, b = bh>>4;
    const int kt = blockIdx.x;

    const __nv_bfloat16* gp[4] = {
        g_Qhi + ((size_t)bh*LQ + q0)*DH, g_Qlo + ((size_t)bh*LQ + q0)*DH,
        g_Khi + ((size_t)bh*LK + k0)*DH, g_Klo + ((size_t)bh*LK + k0)*DH };
#pragma unroll
    for (int t4=0;t4<4;t4++)
#pragma unroll
        for (int i=0;i<4;i++){
            int idx = tid + i*256, row = idx>>3, c = idx&7;
            CP16(sb + t4*TILESZ + row*TSTRIDE + c*16, gp[t4] + (size_t)row*DH + c*8);
        }
    CPCOMMIT(); CPWAIT(0);
    __syncthreads();

    float acc[2][8][4];
#pragma unroll
    for (int a=0;a<2;a++)
#pragma unroll
        for (int c=0;c<8;c++)
#pragma unroll
            for (int d=0;d<4;d++) acc[a][c][d]=0.f;

    const uint32_t aoff = (uint32_t)((wm*32 + (lane&15))*TSTRIDE + (lane>>4)*16);
    const uint32_t boff = (uint32_t)((wn*64 + (lane&7))*TSTRIDE + ((lane>>3)&1)*16);
    const uint32_t TQh = sb, TQl = sb+TILESZ, TKh = sb+2*TILESZ, TKl = sb+3*TILESZ;
#pragma unroll
    for (int ks=0;ks<4;ks++){
        uint32_t ah[2][4], al[2][4];
        ldm_x4(ah[0], TQh + aoff + ks*32);
        ldm_x4(ah[1], TQh + aoff + 16*TSTRIDE + ks*32);
        ldm_x4(al[0], TQl + aoff + ks*32);
        ldm_x4(al[1], TQl + aoff + 16*TSTRIDE + ks*32);
#pragma unroll
        for (int nt=0;nt<8;nt++){
            uint32_t bh2[2], bl2[2];
            ldm_x2(bh2, TKh + boff + nt*8*TSTRIDE + ks*32);
            ldm_x2(bl2, TKl + boff + nt*8*TSTRIDE + ks*32);
#pragma unroll
            for (int mt=0;mt<2;mt++){
                mma16816(acc[mt][nt], ah[mt], bh2);
                mma16816(acc[mt][nt], ah[mt], bl2);
                mma16816(acc[mt][nt], al[mt], bh2);
            }
        }
    }
    __syncthreads();
    {
        const int g = lane>>2, tg = lane&3;
#pragma unroll
        for (int mt=0;mt<2;mt++)
#pragma unroll
            for (int nt=0;nt<8;nt++){
                int row = wm*32 + mt*16 + g;
                int col = wn*64 + nt*8 + tg*2;
                stg[row*132+col] = acc[mt][nt][0];  stg[row*132+col+1] = acc[mt][nt][1];
                stg[(row+8)*132+col] = acc[mt][nt][2]; stg[(row+8)*132+col+1] = acc[mt][nt][3];
            }
    }
    __syncthreads();
    {
        const int r2 = tid>>1, hf = tid&1;
        const int q = q0 + r2;
        float* srow = stg + r2*132 + hf*64;
        const float* brow = bias + ((size_t)bh*LQ + q)*LK + k0 + hf*64;
        const int*   mrow = mask + ((size_t)b*LQ  + q)*LK + k0 + hf*64;
        float mx = -3.0e38f;
#pragma unroll
        for (int j=0;j<16;j++){
            float4 s = *(const float4*)(srow + j*4);
            float4 bb = *(const float4*)(brow + j*4);
            int4   mm = *(const int4*)  (mrow + j*4);
            s.x = mm.x ? s.x+bb.x : -1e9f;
            s.y = mm.y ? s.y+bb.y : -1e9f;
            s.z = mm.z ? s.z+bb.z : -1e9f;
            s.w = mm.w ? s.w+bb.w : -1e9f;
            mx = fmaxf(mx, fmaxf(fmaxf(s.x,s.y), fmaxf(s.z,s.w)));
            *(float4*)(srow + j*4) = s;
        }
        mx = fmaxf(mx, __shfl_xor_sync(0xffffffffu, mx, 1));
        float sum = 0.f;
        float* arow = attn + ((size_t)bh*LQ + q)*LK + k0 + hf*64;
#pragma unroll
        for (int j=0;j<16;j++){
            float4 s = *(const float4*)(srow + j*4);
            float4 e;
            e.x = __expf(s.x-mx); e.y = __expf(s.y-mx);
            e.z = __expf(s.z-mx); e.w = __expf(s.w-mx);
            sum += (e.x+e.y)+(e.z+e.w);
            *(float4*)(arow + j*4) = e;
        }
        sum += __shfl_xor_sync(0xffffffffu, sum, 1);
        if (hf == 0)
            g_pstats[((size_t)bh*LQ + q)*16 + kt] = make_float2(mx, sum);
    }
}

// ============================================================================
// Merge per-row tile partials -> per-tile normalization scales
// ============================================================================
__global__ void __launch_bounds__(256) merge_kernel()
{
    const int row = blockIdx.x*256 + threadIdx.x;   // 0 .. BH*LQ-1
    float2 p[16];
#pragma unroll
    for (int t=0;t<16;t++) p[t] = g_pstats[(size_t)row*16 + t];
    float m = p[0].x;
#pragma unroll
    for (int t=1;t<16;t++) m = fmaxf(m, p[t].x);
    float e[16]; float S = 0.f;
#pragma unroll
    for (int t=0;t<16;t++){ e[t] = __expf(p[t].x - m); S += p[t].y * e[t]; }
    const float inv = 1.f / S;
#pragma unroll
    for (int t=0;t<16;t++) g_scale[(size_t)row*16 + t] = e[t] * inv;
}

// ============================================================================
// PV: reads exp values, multiplies by per-tile scale (no exp), writes
// normalized probs back to attn, MMA P@V^T -> ctx hi/lo.
// smem: Ph@0, Pl@18432, Vh@36864, Vl@46080, stage@55296 (34816), scales@90112 (8KB)
// ============================================================================
#define PV_SMEM (2*TILESZ + 2*9216 + 128*68*4 + 8192)
__global__ void __launch_bounds__(256) pv_kernel(float* __restrict__ attn)
{
    extern __shared__ char smc[];
    const uint32_t sb = smem_u32(smc);
    float* stg = (float*)(smc + 2*TILESZ + 2*9216);
    float* ssc = (float*)(smc + 2*TILESZ + 2*9216 + 34816);
    const int tid = threadIdx.x, lane = tid&31, wid = tid>>5;
    const int wm = wid>>1, wn = wid&1;
    const int q0 = blockIdx.x*128, bh = blockIdx.y, b = bh>>4, h = bh&15;

    const uint32_t TPh = sb, TPl = sb+TILESZ, TVh = sb+2*TILESZ, TVl = TVh+9216;
    float* Pg = attn + ((size_t)bh*LQ + q0)*LK;
    const __nv_bfloat16* Vhg = g_Vthi + (size_t)bh*DH*LK;
    const __nv_bfloat16* Vlg = g_Vtlo + (size_t)bh*DH*LK;

    // preload normalization scales [128 rows x 16 tiles]
#pragma unroll
    for (int i=0;i<8;i++){
        int idx = tid + i*256;
        int r = idx>>4;
        ssc[idx] = g_scale[((size_t)bh*LQ + q0 + r)*16 + (idx&15)];
    }

    float acc[2][4][4];
#pragma unroll
    for (int a=0;a<2;a++)
#pragma unroll
        for (int c=0;c<4;c++)
#pragma unroll
            for (int d=0;d<4;d++) acc[a][c][d]=0.f;

    const uint32_t aoff = (uint32_t)((wm*32 + (lane&15))*TSTRIDE + (lane>>4)*16);
    const uint32_t boff = (uint32_t)((wn*32 + (lane&7))*TSTRIDE + ((lane>>3)&1)*16);

    for (int ck=0; ck<32; ck++){
        const int t0 = ck*64;
        const int kt2 = ck>>1;
        __syncthreads();
        // normalize probs (mul by scale), write back, build P hi/lo tiles
#pragma unroll
        for (int i=0;i<8;i++){
            int idx = tid + i*256, row = idx>>4, c4 = idx&15;
            const float sc = ssc[row*16 + kt2];
            float* pp = Pg + (size_t)row*LK + t0 + c4*4;
            float4 v = *(const float4*)pp;
            v.x *= sc; v.y *= sc; v.z *= sc; v.w *= sc;
            *(float4*)pp = v;
            __nv_bfloat16 h0,l0,h1,l1,h2,l2,h3,l3;
            fsplit(v.x,h0,l0); fsplit(v.y,h1,l1); fsplit(v.z,h2,l2); fsplit(v.w,h3,l3);
            *(uint2*)(smc + (row*TSTRIDE + c4*8))          = make_uint2(pack2(h0,h1),pack2(h2,h3));
            *(uint2*)(smc + TILESZ + (row*TSTRIDE + c4*8)) = make_uint2(pack2(l0,l1),pack2(l2,l3));
        }
        // V tiles
#pragma unroll
        for (int i=0;i<2;i++){
            int idx = tid + i*256, row = idx>>3, c = idx&7;
            CP16(TVh + row*TSTRIDE + c*16, Vhg + (size_t)row*LK + t0 + c*8);
            CP16(TVl + row*TSTRIDE + c*16, Vlg + (size_t)row*LK + t0 + c*8);
        }
        CPCOMMIT(); CPWAIT(0);
        __syncthreads();
#pragma unroll
        for (int ks=0;ks<4;ks++){
            uint32_t ah[2][4], al[2][4];
            ldm_x4(ah[0], TPh + aoff + ks*32);
            ldm_x4(ah[1], TPh + aoff + 16*TSTRIDE + ks*32);
            ldm_x4(al[0], TPl + aoff + ks*32);
            ldm_x4(al[1], TPl + aoff + 16*TSTRIDE + ks*32);
#pragma unroll
            for (int nt=0;nt<4;nt++){
                uint32_t bh2[2], bl2[2];
                ldm_x2(bh2, TVh + boff + nt*8*TSTRIDE + ks*32);
                ldm_x2(bl2, TVl + boff + nt*8*TSTRIDE + ks*32);
#pragma unroll
                for (int mt=0;mt<2;mt++){
                    mma16816(acc[mt][nt], ah[mt], bh2);
                    mma16816(acc[mt][nt], ah[mt], bl2);
                    mma16816(acc[mt][nt], al[mt], bh2);
                }
            }
        }
    }
    __syncthreads();
    {
        const int g = lane>>2, tg = lane&3;
#pragma unroll
        for (int mt=0;mt<2;mt++)
#pragma unroll
            for (int nt=0;nt<4;nt++){
                int row = wm*32 + mt*16 + g;
                int col = wn*32 + nt*8 + tg*2;
                stg[row*68+col] = acc[mt][nt][0];  stg[row*68+col+1] = acc[mt][nt][1];
                stg[(row+8)*68+col] = acc[mt][nt][2]; stg[(row+8)*68+col+1] = acc[mt][nt][3];
            }
    }
    __syncthreads();
    {
        const int r2 = tid>>1, hf = tid&1;
        const float* srow = stg + r2*68 + hf*32;
        size_t base = ((size_t)(b*LQ + q0 + r2))*DM + h*DH + hf*32;
        __nv_bfloat16* ch = g_hi + P_CTX + base;
        __nv_bfloat16* cl = g_lo + P_CTX + base;
#pragma unroll
        for (int j=0;j<4;j++){
            __nv_bfloat16 h0,l0,h1,l1,h2,l2,h3,l3,h4,l4,h5,l5,h6,l6,h7,l7;
            fsplit(srow[j*8+0],h0,l0); fsplit(srow[j*8+1],h1,l1);
            fsplit(srow[j*8+2],h2,l2); fsplit(srow[j*8+3],h3,l3);
            fsplit(srow[j*8+4],h4,l4); fsplit(srow[j*8+5],h5,l5);
            fsplit(srow[j*8+6],h6,l6); fsplit(srow[j*8+7],h7,l7);
            ((uint4*)ch)[j] = make_uint4(pack2(h0,h1),pack2(h2,h3),pack2(h4,h5),pack2(h6,h7));
            ((uint4*)cl)[j] = make_uint4(pack2(l0,l1),pack2(l2,l3),pack2(l4,l5),pack2(l6,l7));
        }
    }
}

// ============================================================================
extern "C" void kernel_launch(void* const* d_in, const int* in_sizes, int n_in,
                              void* d_out, int out_size)
{
    const float* query = (const float*)d_in[0];
    const float* key   = (const float*)d_in[1];
    const float* value = (const float*)d_in[2];
    const int*   mask  = (const int*)  d_in[3];
    const float* abias = (const float*)d_in[4];
    const float* Wq = (const float*)d_in[5];
    const float* bq = (const float*)d_in[6];
    const float* Wk = (const float*)d_in[7];
    const float* bk = (const float*)d_in[8];
    const float* Wv = (const float*)d_in[9];
    const float* bv = (const float*)d_in[10];
    const float* Wo = (const float*)d_in[11];
    const float* bo = (const float*)d_in[12];
    float* out  = (float*)d_out;
    float* attn = out + OUT_ELEMS;

    __nv_bfloat16 *hi, *lo;
    cudaGetSymbolAddress((void**)&hi, g_hi);
    cudaGetSymbolAddress((void**)&lo, g_lo);

    cudaFuncSetAttribute(proj_kernel<0>, cudaFuncAttributeMaxDynamicSharedMemorySize, PROJ_SMEM);
    cudaFuncSetAttribute(proj_kernel<1>, cudaFuncAttributeMaxDynamicSharedMemorySize, PROJ_SMEM);
    cudaFuncSetAttribute(proj_kernel<2>, cudaFuncAttributeMaxDynamicSharedMemorySize, PROJ_SMEM);
    cudaFuncSetAttribute(proj_kernel<3>, cudaFuncAttributeMaxDynamicSharedMemorySize, PROJ_SMEM);
    cudaFuncSetAttribute(scores_kernel,  cudaFuncAttributeMaxDynamicSharedMemorySize, SC_SMEM);
    cudaFuncSetAttribute(pv_kernel,      cudaFuncAttributeMaxDynamicSharedMemorySize, PV_SMEM);

    struct { const float* s; int off; int n; } cv[7] = {
        {query, P_QUERY, B_*LQ*DM}, {key, P_KEY, B_*LK*DM}, {value, P_VALUE, B_*LK*DM},
        {Wq, P_WQ, DM*DM}, {Wk, P_WK, DM*DM}, {Wv, P_WV, DM*DM}, {Wo, P_WO, DM*DM}};
    for (int i=0;i<7;i++){
        int n4 = cv[i].n/4;
        cvt_kernel<<<(n4+255)/256, 256>>>((const float4*)cv[i].s,
            (uint2*)(hi+cv[i].off), (uint2*)(lo+cv[i].off), n4);
    }

    proj_kernel<0><<<dim3(8,16), 256, PROJ_SMEM>>>(hi+P_QUERY, lo+P_QUERY, hi+P_WQ, lo+P_WQ, bq, nullptr, LQ);
    proj_kernel<1><<<dim3(8,32), 256, PROJ_SMEM>>>(hi+P_KEY,   lo+P_KEY,   hi+P_WK, lo+P_WK, bk, nullptr, LK);
    proj_kernel<2><<<dim3(8,32), 256, PROJ_SMEM>>>(hi+P_VALUE, lo+P_VALUE, hi+P_WV, lo+P_WV, bv, nullptr, LK);

    scores_kernel<<<dim3(LK/128, LQ/128, BH), 256, SC_SMEM>>>(abias, mask, attn);
    merge_kernel<<<(BH*LQ)/256, 256>>>();
    pv_kernel<<<dim3(LQ/128, BH), 256, PV_SMEM>>>(attn);

    proj_kernel<3><<<dim3(8,16), 256, PROJ_SMEM>>>(hi+P_CTX, lo+P_CTX, hi+P_WO, lo+P_WO, bo, out, LQ);
}

// round 10
// speedup vs baseline: 2.2242x; 1.0788x over previous
#include <cuda_runtime.h>
#include <cuda_bf16.h>
#include <cstdint>

#define B_  2
#define LQ  1024
#define LK  2048
#define DM  1024
#define NH  16
#define DH  64
#define BH  (B_*NH)
#define OUT_ELEMS (B_*LQ*DM)

// bf16 hi/lo pools (element offsets)
#define P_QUERY 0
#define P_KEY   (2*1024*1024)
#define P_VALUE (6*1024*1024)
#define P_WQ    (10*1024*1024)
#define P_WK    (11*1024*1024)
#define P_WV    (12*1024*1024)
#define P_WO    (13*1024*1024)
#define P_CTX   (14*1024*1024)
#define P_TOTAL (16*1024*1024)

__device__ __align__(256) __nv_bfloat16 g_hi[P_TOTAL];
__device__ __align__(256) __nv_bfloat16 g_lo[P_TOTAL];
__device__ __align__(256) __nv_bfloat16 g_Qhi[BH*LQ*DH];
__device__ __align__(256) __nv_bfloat16 g_Qlo[BH*LQ*DH];
__device__ __align__(256) __nv_bfloat16 g_Khi[BH*LK*DH];
__device__ __align__(256) __nv_bfloat16 g_Klo[BH*LK*DH];
__device__ __align__(256) __nv_bfloat16 g_Vthi[BH*DH*LK];   // [bh, d, t]
__device__ __align__(256) __nv_bfloat16 g_Vtlo[BH*DH*LK];
__device__ __align__(256) float2        g_pstats[BH*LQ*16]; // per-tile (max, sumexp)
__device__ __align__(256) float         g_scale[BH*LQ*16];  // exp(m_t-m)/S

// ---------------- low-level helpers ----------------------------------------
__device__ __forceinline__ uint32_t smem_u32(const void* p){
    uint32_t a;
    asm("{ .reg .u64 t; cvta.to.shared.u64 t, %1; cvt.u32.u64 %0, t; }" : "=r"(a) : "l"(p));
    return a;
}
#define CP16(d,s) asm volatile("cp.async.cg.shared.global [%0], [%1], 16;" :: "r"(d), "l"(__cvta_generic_to_global(s)))
#define CPCOMMIT() asm volatile("cp.async.commit_group;" ::: "memory")
#define CPWAIT(n)  asm volatile("cp.async.wait_group %0;" :: "n"(n) : "memory")

__device__ __forceinline__ void ldm_x4(uint32_t* r, uint32_t a){
    asm volatile("ldmatrix.sync.aligned.m8n8.x4.shared.b16 {%0,%1,%2,%3}, [%4];"
        : "=r"(r[0]),"=r"(r[1]),"=r"(r[2]),"=r"(r[3]) : "r"(a));
}
__device__ __forceinline__ void ldm_x2(uint32_t* r, uint32_t a){
    asm volatile("ldmatrix.sync.aligned.m8n8.x2.shared.b16 {%0,%1}, [%2];"
        : "=r"(r[0]),"=r"(r[1]) : "r"(a));
}
__device__ __forceinline__ void mma16816(float* d, const uint32_t* a, const uint32_t* b){
    asm volatile("mma.sync.aligned.m16n8k16.row.col.f32.bf16.bf16.f32 "
        "{%0,%1,%2,%3}, {%4,%5,%6,%7}, {%8,%9}, {%0,%1,%2,%3};"
        : "+f"(d[0]),"+f"(d[1]),"+f"(d[2]),"+f"(d[3])
        : "r"(a[0]),"r"(a[1]),"r"(a[2]),"r"(a[3]), "r"(b[0]),"r"(b[1]));
}
__device__ __forceinline__ void fsplit(float x, __nv_bfloat16& h, __nv_bfloat16& l){
    h = __float2bfloat16(x);
    l = __float2bfloat16(x - __bfloat162float(h));
}
__device__ __forceinline__ uint32_t pack2(__nv_bfloat16 a, __nv_bfloat16 b){
    return (uint32_t)__bfloat16_as_ushort(a) | ((uint32_t)__bfloat16_as_ushort(b) << 16);
}

// ---------------- fused input conversion fp32 -> bf16 hi/lo ------------------
// segments (float4 counts): q 524288 | k 1048576 | v 1048576 | wq,wk,wv,wo 262144 each
__global__ void __launch_bounds__(256) cvt_all(
    const float4* __restrict__ q, const float4* __restrict__ k, const float4* __restrict__ v,
    const float4* __restrict__ wq, const float4* __restrict__ wk,
    const float4* __restrict__ wv, const float4* __restrict__ wo)
{
    int i = blockIdx.x*256 + threadIdx.x;
    const float4* src; size_t dst;
    if      (i < 524288)  { src = q  + i;             dst = P_QUERY/4 + i; }
    else if (i < 1572864) { src = k  + (i-524288);    dst = P_KEY/4   + (i-524288); }
    else if (i < 2621440) { src = v  + (i-1572864);   dst = P_VALUE/4 + (i-1572864); }
    else if (i < 2883584) { src = wq + (i-2621440);   dst = P_WQ/4    + (i-2621440); }
    else if (i < 3145728) { src = wk + (i-2883584);   dst = P_WK/4    + (i-2883584); }
    else if (i < 3407872) { src = wv + (i-3145728);   dst = P_WV/4    + (i-3145728); }
    else                  { src = wo + (i-3407872);   dst = P_WO/4    + (i-3407872); }
    float4 x = *src;
    __nv_bfloat16 h0,l0,h1,l1,h2,l2,h3,l3;
    fsplit(x.x,h0,l0); fsplit(x.y,h1,l1); fsplit(x.z,h2,l2); fsplit(x.w,h3,l3);
    ((uint2*)g_hi)[dst] = make_uint2(pack2(h0,h1), pack2(h2,h3));
    ((uint2*)g_lo)[dst] = make_uint2(pack2(l0,l1), pack2(l2,l3));
}

// ============================================================================
// Projection body: C[128x128] = A @ W^T + bias. Single-buffered tiles, stage
// overlays the tile region. smem = 512 + 4*TILESZ = 74240 B -> 2+ CTAs/SM.
// mode 0: Q (scale 1/8 -> g_Q hi/lo), 1: K, 2: V (transposed), 3: O fp32
// ============================================================================
#define TSTRIDE 144
#define TILESZ  18432
#define PROJ_SMEM (512 + 4*TILESZ)

__device__ __forceinline__ void proj_body(
    int mode, int m0, int n0,
    const __nv_bfloat16* __restrict__ Ah_g, const __nv_bfloat16* __restrict__ Al_g,
    const __nv_bfloat16* __restrict__ Wh_g, const __nv_bfloat16* __restrict__ Wl_g,
    const float* __restrict__ bias, float* __restrict__ outp, int Ltok)
{
    extern __shared__ char smc[];
    const uint32_t sb = smem_u32(smc);
    const uint32_t tbase = sb + 512;
    float* bias_sm = (float*)smc;
    float* stg = (float*)(smc + 512);       // overlays tiles (used after MMA)

    const int tid = threadIdx.x, lane = tid&31, wid = tid>>5;
    const int wm = wid>>1, wn = wid&1;

    if (tid < 128) bias_sm[tid] = bias[n0+tid];

    const __nv_bfloat16* gp[4] = {
        Ah_g + (size_t)m0*DM, Al_g + (size_t)m0*DM,
        Wh_g + (size_t)n0*DM, Wl_g + (size_t)n0*DM };

    float acc[2][8][4];
#pragma unroll
    for (int a=0;a<2;a++)
#pragma unroll
        for (int b=0;b<8;b++)
#pragma unroll
            for (int c=0;c<4;c++) acc[a][b][c]=0.f;

    const uint32_t aoff = (uint32_t)((wm*32 + (lane&15))*TSTRIDE + (lane>>4)*16);
    const uint32_t boff = (uint32_t)((wn*64 + (lane&7))*TSTRIDE + ((lane>>3)&1)*16);

    for (int ck=0; ck<16; ck++){
#pragma unroll
        for (int t4=0;t4<4;t4++)
#pragma unroll
            for (int i=0;i<4;i++){
                int idx = tid + i*256, row = idx>>3, c = idx&7;
                CP16(tbase + t4*TILESZ + row*TSTRIDE + c*16,
                     gp[t4] + (size_t)row*DM + ck*64 + c*8);
            }
        CPCOMMIT(); CPWAIT(0);
        __syncthreads();

        const uint32_t TA  = tbase;
        const uint32_t TAl = TA + TILESZ, TW = TA + 2*TILESZ, TWl = TA + 3*TILESZ;
#pragma unroll
        for (int ks=0;ks<4;ks++){
            uint32_t ah[2][4], al[2][4];
            ldm_x4(ah[0], TA  + aoff + ks*32);
            ldm_x4(ah[1], TA  + aoff + 16*TSTRIDE + ks*32);
            ldm_x4(al[0], TAl + aoff + ks*32);
            ldm_x4(al[1], TAl + aoff + 16*TSTRIDE + ks*32);
#pragma unroll
            for (int nt=0;nt<8;nt++){
                uint32_t bh[2], bl[2];
                ldm_x2(bh, TW  + boff + nt*8*TSTRIDE + ks*32);
                ldm_x2(bl, TWl + boff + nt*8*TSTRIDE + ks*32);
#pragma unroll
                for (int mt=0;mt<2;mt++){
                    mma16816(acc[mt][nt], ah[mt], bh);
                    mma16816(acc[mt][nt], ah[mt], bl);
                    mma16816(acc[mt][nt], al[mt], bh);
                }
            }
        }
        __syncthreads();
    }

    // stage accumulators (+bias, Q scale) into fp32 smem (overlays tiles)
    {
        const int g = lane>>2, tg = lane&3;
#pragma unroll
        for (int mt=0;mt<2;mt++)
#pragma unroll
            for (int nt=0;nt<8;nt++){
                int row = wm*32 + mt*16 + g;
                int col = wn*64 + nt*8 + tg*2;
                float b0 = bias_sm[col], b1 = bias_sm[col+1];
                float v0 = acc[mt][nt][0]+b0, v1 = acc[mt][nt][1]+b1;
                float v2 = acc[mt][nt][2]+b0, v3 = acc[mt][nt][3]+b1;
                if (mode==0){ v0*=0.125f; v1*=0.125f; v2*=0.125f; v3*=0.125f; }
                stg[row*132+col] = v0;  stg[row*132+col+1] = v1;
                stg[(row+8)*132+col] = v2; stg[(row+8)*132+col+1] = v3;
            }
    }
    __syncthreads();

    if (mode==3){
        const int r2 = tid>>1, hf = tid&1;
        const float* srow = stg + r2*132 + hf*64;
        float* drow = outp + (size_t)(m0+r2)*DM + n0 + hf*64;
#pragma unroll
        for (int j=0;j<16;j++) *(float4*)(drow + j*4) = *(const float4*)(srow + j*4);
    } else if (mode<2){
        const int r2 = tid>>1, hf = tid&1;
        const int rowg = m0 + r2;
        const int b = rowg / Ltok, tok = rowg - b*Ltok;
        const int h = (n0>>6) + hf;
        const float* srow = stg + r2*132 + hf*64;
        __nv_bfloat16* gh = ((mode==0)? g_Qhi : g_Khi) + ((size_t)(b*NH+h)*Ltok + tok)*DH;
        __nv_bfloat16* gl = ((mode==0)? g_Qlo : g_Klo) + ((size_t)(b*NH+h)*Ltok + tok)*DH;
#pragma unroll
        for (int j=0;j<8;j++){
            __nv_bfloat16 h0,l0,h1,l1,h2,l2,h3,l3,h4,l4,h5,l5,h6,l6,h7,l7;
            fsplit(srow[j*8+0],h0,l0); fsplit(srow[j*8+1],h1,l1);
            fsplit(srow[j*8+2],h2,l2); fsplit(srow[j*8+3],h3,l3);
            fsplit(srow[j*8+4],h4,l4); fsplit(srow[j*8+5],h5,l5);
            fsplit(srow[j*8+6],h6,l6); fsplit(srow[j*8+7],h7,l7);
            ((uint4*)gh)[j] = make_uint4(pack2(h0,h1),pack2(h2,h3),pack2(h4,h5),pack2(h6,h7));
            ((uint4*)gl)[j] = make_uint4(pack2(l0,l1),pack2(l2,l3),pack2(l4,l5),pack2(l6,l7));
        }
    } else {
        const int dl = tid>>1, th = tid&1;
        const int dg = n0 + dl, h = dg>>6, dd = dg&63;
        const int b = m0 / Ltok, toff = m0 - b*Ltok;
        __nv_bfloat16* vh = g_Vthi + ((size_t)(b*NH+h)*DH + dd)*LK + toff + th*64;
        __nv_bfloat16* vl = g_Vtlo + ((size_t)(b*NH+h)*DH + dd)*LK + toff + th*64;
#pragma unroll
        for (int j=0;j<16;j++){
            int t4 = th*64 + j*4;
            __nv_bfloat16 h0,l0,h1,l1,h2,l2,h3,l3;
            fsplit(stg[(t4+0)*132+dl],h0,l0);
            fsplit(stg[(t4+1)*132+dl],h1,l1);
            fsplit(stg[(t4+2)*132+dl],h2,l2);
            fsplit(stg[(t4+3)*132+dl],h3,l3);
            ((uint2*)vh)[j] = make_uint2(pack2(h0,h1), pack2(h2,h3));
            ((uint2*)vl)[j] = make_uint2(pack2(l0,l1), pack2(l2,l3));
        }
    }
}

// fused Q/K/V projection: grid (8, 80): y<16 Q, y<48 K, else V
__global__ void __launch_bounds__(256,2) qkv_kernel(
    const float* __restrict__ bq, const float* __restrict__ bk, const float* __restrict__ bv)
{
    const int my = blockIdx.y, n0 = blockIdx.x*128;
    if (my < 16)
        proj_body(0, my*128, n0, g_hi+P_QUERY, g_lo+P_QUERY, g_hi+P_WQ, g_lo+P_WQ, bq, nullptr, LQ);
    else if (my < 48)
        proj_body(1, (my-16)*128, n0, g_hi+P_KEY, g_lo+P_KEY, g_hi+P_WK, g_lo+P_WK, bk, nullptr, LK);
    else
        proj_body(2, (my-48)*128, n0, g_hi+P_VALUE, g_lo+P_VALUE, g_hi+P_WV, g_lo+P_WV, bv, nullptr, LK);
}

__global__ void __launch_bounds__(256,2) oproj_kernel(const float* __restrict__ bo, float* __restrict__ out)
{
    proj_body(3, blockIdx.y*128, blockIdx.x*128,
              g_hi+P_CTX, g_lo+P_CTX, g_hi+P_WO, g_lo+P_WO, bo, out, LQ);
}

// ============================================================================
// Scores: S = Q@K^T + bias, mask; writes exp(s-m_tile) to attn, per-tile
// (max,sum) -> g_pstats. Stage overlays tiles: smem = 4*TILESZ = 73728 B.
// ============================================================================
#define SC_SMEM (4*TILESZ)
__global__ void __launch_bounds__(256,2) scores_kernel(
    const float* __restrict__ bias, const int* __restrict__ mask,
    float* __restrict__ attn)
{
    extern __shared__ char smc[];
    const uint32_t sb = smem_u32(smc);
    float* stg = (float*)smc;               // overlays tiles (used after MMA)
    const int tid = threadIdx.x, lane = tid&31, wid = tid>>5;
    const int wm = wid>>1, wn = wid&1;
    const int k0 = blockIdx.x*128, q0 = blockIdx.y*128, bh = blockIdx.z, b = bh>>4;
    const int kt = blockIdx.x;

    const __nv_bfloat16* gp[4] = {
        g_Qhi + ((size_t)bh*LQ + q0)*DH, g_Qlo + ((size_t)bh*LQ + q0)*DH,
        g_Khi + ((size_t)bh*LK + k0)*DH, g_Klo + ((size_t)bh*LK + k0)*DH };
#pragma unroll
    for (int t4=0;t4<4;t4++)
#pragma unroll
        for (int i=0;i<4;i++){
            int idx = tid + i*256, row = idx>>3, c = idx&7;
            CP16(sb + t4*TILESZ + row*TSTRIDE + c*16, gp[t4] + (size_t)row*DH + c*8);
        }
    CPCOMMIT(); CPWAIT(0);
    __syncthreads();

    float acc[2][8][4];
#pragma unroll
    for (int a=0;a<2;a++)
#pragma unroll
        for (int c=0;c<8;c++)
#pragma unroll
            for (int d=0;d<4;d++) acc[a][c][d]=0.f;

    const uint32_t aoff = (uint32_t)((wm*32 + (lane&15))*TSTRIDE + (lane>>4)*16);
    const uint32_t boff = (uint32_t)((wn*64 + (lane&7))*TSTRIDE + ((lane>>3)&1)*16);
    const uint32_t TQh = sb, TQl = sb+TILESZ, TKh = sb+2*TILESZ, TKl = sb+3*TILESZ;
#pragma unroll
    for (int ks=0;ks<4;ks++){
        uint32_t ah[2][4], al[2][4];
        ldm_x4(ah[0], TQh + aoff + ks*32);
        ldm_x4(ah[1], TQh + aoff + 16*TSTRIDE + ks*32);
        ldm_x4(al[0], TQl + aoff + ks*32);
        ldm_x4(al[1], TQl + aoff + 16*TSTRIDE + ks*32);
#pragma unroll
        for (int nt=0;nt<8;nt++){
            uint32_t bh2[2], bl2[2];
            ldm_x2(bh2, TKh + boff + nt*8*TSTRIDE + ks*32);
            ldm_x2(bl2, TKl + boff + nt*8*TSTRIDE + ks*32);
#pragma unroll
            for (int mt=0;mt<2;mt++){
                mma16816(acc[mt][nt], ah[mt], bh2);
                mma16816(acc[mt][nt], ah[mt], bl2);
                mma16816(acc[mt][nt], al[mt], bh2);
            }
        }
    }
    __syncthreads();   // tiles dead; stage overlays them
    {
        const int g = lane>>2, tg = lane&3;
#pragma unroll
        for (int mt=0;mt<2;mt++)
#pragma unroll
            for (int nt=0;nt<8;nt++){
                int row = wm*32 + mt*16 + g;
                int col = wn*64 + nt*8 + tg*2;
                stg[row*132+col] = acc[mt][nt][0];  stg[row*132+col+1] = acc[mt][nt][1];
                stg[(row+8)*132+col] = acc[mt][nt][2]; stg[(row+8)*132+col+1] = acc[mt][nt][3];
            }
    }
    __syncthreads();
    {
        const int r2 = tid>>1, hf = tid&1;
        const int q = q0 + r2;
        float* srow = stg + r2*132 + hf*64;
        const float* brow = bias + ((size_t)bh*LQ + q)*LK + k0 + hf*64;
        const int*   mrow = mask + ((size_t)b*LQ  + q)*LK + k0 + hf*64;
        float mx = -3.0e38f;
#pragma unroll
        for (int j=0;j<16;j++){
            float4 s = *(const float4*)(srow + j*4);
            float4 bb = *(const float4*)(brow + j*4);
            int4   mm = *(const int4*)  (mrow + j*4);
            s.x = mm.x ? s.x+bb.x : -1e9f;
            s.y = mm.y ? s.y+bb.y : -1e9f;
            s.z = mm.z ? s.z+bb.z : -1e9f;
            s.w = mm.w ? s.w+bb.w : -1e9f;
            mx = fmaxf(mx, fmaxf(fmaxf(s.x,s.y), fmaxf(s.z,s.w)));
            *(float4*)(srow + j*4) = s;
        }
        mx = fmaxf(mx, __shfl_xor_sync(0xffffffffu, mx, 1));
        float sum = 0.f;
        float* arow = attn + ((size_t)bh*LQ + q)*LK + k0 + hf*64;
#pragma unroll
        for (int j=0;j<16;j++){
            float4 s = *(const float4*)(srow + j*4);
            float4 e;
            e.x = __expf(s.x-mx); e.y = __expf(s.y-mx);
            e.z = __expf(s.z-mx); e.w = __expf(s.w-mx);
            sum += (e.x+e.y)+(e.z+e.w);
            *(float4*)(arow + j*4) = e;
        }
        sum += __shfl_xor_sync(0xffffffffu, sum, 1);
        if (hf == 0)
            g_pstats[((size_t)bh*LQ + q)*16 + kt] = make_float2(mx, sum);
    }
}

// ============================================================================
// Merge per-row tile partials -> per-tile normalization scales
// ============================================================================
__global__ void __launch_bounds__(256) merge_kernel()
{
    const int row = blockIdx.x*256 + threadIdx.x;
    float2 p[16];
#pragma unroll
    for (int t=0;t<16;t++) p[t] = g_pstats[(size_t)row*16 + t];
    float m = p[0].x;
#pragma unroll
    for (int t=1;t<16;t++) m = fmaxf(m, p[t].x);
    float e[16]; float S = 0.f;
#pragma unroll
    for (int t=0;t<16;t++){ e[t] = __expf(p[t].x - m); S += p[t].y * e[t]; }
    const float inv = 1.f / S;
#pragma unroll
    for (int t=0;t<16;t++) g_scale[(size_t)row*16 + t] = e[t] * inv;
}

// ============================================================================
// PV: exp values * per-tile scale -> normalized probs (written back) + MMA.
// smem: TPh@0, TPl@18432, TVh@36864, TVl@46080, ssc@55296 (8KB) = 63488 B.
// stage (34816 B) overlays TPh/TPl after final MMA.
// ============================================================================
#define PV_SMEM (2*TILESZ + 2*9216 + 8192)
__global__ void __launch_bounds__(256,2) pv_kernel(float* __restrict__ attn)
{
    extern __shared__ char smc[];
    const uint32_t sb = smem_u32(smc);
    float* stg = (float*)smc;               // overlays P tiles at the end
    float* ssc = (float*)(smc + 2*TILESZ + 2*9216);
    const int tid = threadIdx.x, lane = tid&31, wid = tid>>5;
    const int wm = wid>>1, wn = wid&1;
    const int q0 = blockIdx.x*128, bh = blockIdx.y, b = bh>>4, h = bh&15;

    const uint32_t TPh = sb, TPl = sb+TILESZ, TVh = sb+2*TILESZ, TVl = TVh+9216;
    float* Pg = attn + ((size_t)bh*LQ + q0)*LK;
    const __nv_bfloat16* Vhg = g_Vthi + (size_t)bh*DH*LK;
    const __nv_bfloat16* Vlg = g_Vtlo + (size_t)bh*DH*LK;

#pragma unroll
    for (int i=0;i<8;i++){
        int idx = tid + i*256;
        int r = idx>>4;
        ssc[idx] = g_scale[((size_t)bh*LQ + q0 + r)*16 + (idx&15)];
    }

    float acc[2][4][4];
#pragma unroll
    for (int a=0;a<2;a++)
#pragma unroll
        for (int c=0;c<4;c++)
#pragma unroll
            for (int d=0;d<4;d++) acc[a][c][d]=0.f;

    const uint32_t aoff = (uint32_t)((wm*32 + (lane&15))*TSTRIDE + (lane>>4)*16);
    const uint32_t boff = (uint32_t)((wn*32 + (lane&7))*TSTRIDE + ((lane>>3)&1)*16);

    for (int ck=0; ck<32; ck++){
        const int t0 = ck*64;
        const int kt2 = ck>>1;
        __syncthreads();
#pragma unroll
        for (int i=0;i<8;i++){
            int idx = tid + i*256, row = idx>>4, c4 = idx&15;
            const float sc = ssc[row*16 + kt2];
            float* pp = Pg + (size_t)row*LK + t0 + c4*4;
            float4 v = *(const float4*)pp;
            v.x *= sc; v.y *= sc; v.z *= sc; v.w *= sc;
            *(float4*)pp = v;
            __nv_bfloat16 h0,l0,h1,l1,h2,l2,h3,l3;
            fsplit(v.x,h0,l0); fsplit(v.y,h1,l1); fsplit(v.z,h2,l2); fsplit(v.w,h3,l3);
            *(uint2*)(smc + (row*TSTRIDE + c4*8))          = make_uint2(pack2(h0,h1),pack2(h2,h3));
            *(uint2*)(smc + TILESZ + (row*TSTRIDE + c4*8)) = make_uint2(pack2(l0,l1),pack2(l2,l3));
        }
#pragma unroll
        for (int i=0;i<2;i++){
            int idx = tid + i*256, row = idx>>3, c = idx&7;
            CP16(TVh + row*TSTRIDE + c*16, Vhg + (size_t)row*LK + t0 + c*8);
            CP16(TVl + row*TSTRIDE + c*16, Vlg + (size_t)row*LK + t0 + c*8);
        }
        CPCOMMIT(); CPWAIT(0);
        __syncthreads();
#pragma unroll
        for (int ks=0;ks<4;ks++){
            uint32_t ah[2][4], al[2][4];
            ldm_x4(ah[0], TPh + aoff + ks*32);
            ldm_x4(ah[1], TPh + aoff + 16*TSTRIDE + ks*32);
            ldm_x4(al[0], TPl + aoff + ks*32);
            ldm_x4(al[1], TPl + aoff + 16*TSTRIDE + ks*32);
#pragma unroll
            for (int nt=0;nt<4;nt++){
                uint32_t bh2[2], bl2[2];
                ldm_x2(bh2, TVh + boff + nt*8*TSTRIDE + ks*32);
                ldm_x2(bl2, TVl + boff + nt*8*TSTRIDE + ks*32);
#pragma unroll
                for (int mt=0;mt<2;mt++){
                    mma16816(acc[mt][nt], ah[mt], bh2);
                    mma16816(acc[mt][nt], ah[mt], bl2);
                    mma16816(acc[mt][nt], al[mt], bh2);
                }
            }
        }
    }
    __syncthreads();   // P tiles dead; stage overlays
    {
        const int g = lane>>2, tg = lane&3;
#pragma unroll
        for (int mt=0;mt<2;mt++)
#pragma unroll
            for (int nt=0;nt<4;nt++){
                int row = wm*32 + mt*16 + g;
                int col = wn*32 + nt*8 + tg*2;
                stg[row*68+col] = acc[mt][nt][0];  stg[row*68+col+1] = acc[mt][nt][1];
                stg[(row+8)*68+col] = acc[mt][nt][2]; stg[(row+8)*68+col+1] = acc[mt][nt][3];
            }
    }
    __syncthreads();
    {
        const int r2 = tid>>1, hf = tid&1;
        const float* srow = stg + r2*68 + hf*32;
        size_t base = ((size_t)(b*LQ + q0 + r2))*DM + h*DH + hf*32;
        __nv_bfloat16* ch = g_hi + P_CTX + base;
        __nv_bfloat16* cl = g_lo + P_CTX + base;
#pragma unroll
        for (int j=0;j<4;j++){
            __nv_bfloat16 h0,l0,h1,l1,h2,l2,h3,l3,h4,l4,h5,l5,h6,l6,h7,l7;
            fsplit(srow[j*8+0],h0,l0); fsplit(srow[j*8+1],h1,l1);
            fsplit(srow[j*8+2],h2,l2); fsplit(srow[j*8+3],h3,l3);
            fsplit(srow[j*8+4],h4,l4); fsplit(srow[j*8+5],h5,l5);
            fsplit(srow[j*8+6],h6,l6); fsplit(srow[j*8+7],h7,l7);
            ((uint4*)ch)[j] = make_uint4(pack2(h0,h1),pack2(h2,h3),pack2(h4,h5),pack2(h6,h7));
            ((uint4*)cl)[j] = make_uint4(pack2(l0,l1),pack2(l2,l3),pack2(l4,l5),pack2(l6,l7));
        }
    }
}

// ============================================================================
extern "C" void kernel_launch(void* const* d_in, const int* in_sizes, int n_in,
                              void* d_out, int out_size)
{
    const float* query = (const float*)d_in[0];
    const float* key   = (const float*)d_in[1];
    const float* value = (const float*)d_in[2];
    const int*   mask  = (const int*)  d_in[3];
    const float* abias = (const float*)d_in[4];
    const float* Wq = (const float*)d_in[5];
    const float* bq = (const float*)d_in[6];
    const float* Wk = (const float*)d_in[7];
    const float* bk = (const float*)d_in[8];
    const float* Wv = (const float*)d_in[9];
    const float* bv = (const float*)d_in[10];
    const float* Wo = (const float*)d_in[11];
    const float* bo = (const float*)d_in[12];
    float* out  = (float*)d_out;
    float* attn = out + OUT_ELEMS;

    cudaFuncSetAttribute(qkv_kernel,    cudaFuncAttributeMaxDynamicSharedMemorySize, PROJ_SMEM);
    cudaFuncSetAttribute(oproj_kernel,  cudaFuncAttributeMaxDynamicSharedMemorySize, PROJ_SMEM);
    cudaFuncSetAttribute(scores_kernel, cudaFuncAttributeMaxDynamicSharedMemorySize, SC_SMEM);
    cudaFuncSetAttribute(pv_kernel,     cudaFuncAttributeMaxDynamicSharedMemorySize, PV_SMEM);

    cvt_all<<<14336, 256>>>((const float4*)query, (const float4*)key, (const float4*)value,
                            (const float4*)Wq, (const float4*)Wk, (const float4*)Wv, (const float4*)Wo);

    qkv_kernel<<<dim3(8,80), 256, PROJ_SMEM>>>(bq, bk, bv);

    scores_kernel<<<dim3(LK/128, LQ/128, BH), 256, SC_SMEM>>>(abias, mask, attn);
    merge_kernel<<<(BH*LQ)/256, 256>>>();
    pv_kernel<<<dim3(LQ/128, BH), 256, PV_SMEM>>>(attn);

    oproj_kernel<<<dim3(8,16), 256, PROJ_SMEM>>>(bo, out);
}